// round 16
// baseline (speedup 1.0000x reference)
#include <cuda_runtime.h>
#include <cuda_bf16.h>
#include <cuda_fp16.h>
#include <stdint.h>

#define BB   8192
#define GG   900
#define NC   10
#define HID  128

/* ---- enc1 phase: e5m2 weights, 32-cell chunks ---- */
#define E1_CHUNK 32
#define E1_ROWB  (NC*HID)             /* 1280 */
#define E1_STAGE (E1_CHUNK*E1_ROWB)   /* 40960; buf0 @0, buf1 @40960 */
#define E1_COLORS (2*E1_STAGE)        /* colors @81920, 64*912 bytes */
#define E1_CPAD  912

/* ---- transposed padded weight blob W^T[N][K+8] bf16 (byte offsets) ---- */
#define WT_ENC2 0
#define WT_WY   34816
#define WT_WZ   69632
#define WT_RZ1  87040
#define WT_RZ2  114688
#define WT_RY1  123904
#define WT_RY2  151552
#define WT_SEL1 169984
#define WT_SEL2 187392
#define WT_TOTAL 196608

/* ---- fused SMEM (bytes) ---- */
#define RS_BIAS 0
#define RS_H1   3072
#define RS_H2   20480
#define RS_CAT  37888
#define RS_T    65536
#define RS_WD0  74752
#define RS_WD1  109568
#define RS_RZ1  144384
#define RS_RZ2  172032
#define RS_RY1  181248
#define RS_RY2  208896
#define RS_TOTAL 227328

#define BO_ENC2 0
#define BO_Y    128
#define BO_Z    256
#define BO_RZ1  320
#define BO_RZ2  384
#define BO_RY1  448
#define BO_RY2  512
#define BO_SEL1 640
#define BO_SEL2 704

static __device__ __align__(16) unsigned char g_w1e[GG*NC*HID];
static __device__ __align__(16) __nv_bfloat16 g_wt[WT_TOTAL/2];
static __device__ int g_is64;

__device__ __forceinline__ float gelu_f(float x){
    return 0.5f * x * (1.0f + erff(x * 0.7071067811865476f));
}
__device__ __forceinline__ unsigned pack_bf2(float lo, float hi){
    unsigned d; asm("cvt.rn.bf16x2.f32 %0, %1, %2;" : "=r"(d) : "f"(hi), "f"(lo)); return d;
}
__device__ __forceinline__ unsigned hfma2(unsigned a, unsigned b, unsigned c){
    unsigned d; asm("fma.rn.f16x2 %0, %1, %2, %3;" : "=r"(d) : "r"(a), "r"(b), "r"(c)); return d;
}
__device__ __forceinline__ unsigned prmt(unsigned v, unsigned sel){
    unsigned d; asm("prmt.b32 %0, %1, 0, %2;" : "=r"(d) : "r"(v), "r"(sel)); return d;
}

#define CP_COMMIT() asm volatile("cp.async.commit_group;" ::: "memory")
#define CP_WAIT(N)  asm volatile("cp.async.wait_group %0;" :: "n"(N) : "memory")

__device__ __forceinline__ void cp16(uint32_t d, const void* s){
    asm volatile("cp.async.ca.shared.global [%0], [%1], 16;" :: "r"(d), "l"(s));
}
__device__ __forceinline__ void cpa(uint32_t dst, const void* src, int bytes, int tid, int nthr){
    const char* s = (const char*)src;
    for (int off = tid*16; off < bytes; off += nthr*16) cp16(dst + off, s + off);
}

/* ---- mma.sync / ldmatrix ---- */
__device__ __forceinline__ uint4 ldm4(uint32_t a){
    uint4 r;
    asm volatile("ldmatrix.sync.aligned.m8n8.x4.shared.b16 {%0,%1,%2,%3}, [%4];"
        : "=r"(r.x), "=r"(r.y), "=r"(r.z), "=r"(r.w) : "r"(a));
    return r;
}
__device__ __forceinline__ void mma16816(float (&c)[4], const uint4& a, uint32_t b0, uint32_t b1){
    asm volatile("mma.sync.aligned.m16n8k16.row.col.f32.bf16.bf16.f32 "
        "{%0,%1,%2,%3},{%4,%5,%6,%7},{%8,%9},{%0,%1,%2,%3};"
        : "+f"(c[0]), "+f"(c[1]), "+f"(c[2]), "+f"(c[3])
        : "r"(a.x), "r"(a.y), "r"(a.z), "r"(a.w), "r"(b0), "r"(b1));
}

template<int KS, int NT>
__device__ __forceinline__ void gemm(float (&acc)[NT][4], uint32_t aLane, uint32_t wLane, int wStr){
    #pragma unroll
    for (int ks = 0; ks < KS; ks++){
        uint4 A = ldm4(aLane + ks*32);
        #pragma unroll
        for (int p = 0; p < NT/2; p++){
            uint4 B = ldm4(wLane + p*16*wStr + ks*32);
            mma16816(acc[2*p],   A, B.x, B.y);
            mma16816(acc[2*p+1], A, B.z, B.w);
        }
    }
}
template<int NT>
__device__ __forceinline__ void initacc(float (&acc)[NT][4], const float* bias, int t){
    #pragma unroll
    for (int nt = 0; nt < NT; nt++){
        float b0 = bias[nt*8 + 2*t], b1 = bias[nt*8 + 2*t + 1];
        acc[nt][0] = b0; acc[nt][1] = b1; acc[nt][2] = b0; acc[nt][3] = b1;
    }
}
template<int NT, bool ACT>
__device__ __forceinline__ void storeacc(float (&acc)[NT][4], uint32_t oL0, uint32_t oL1){
    #pragma unroll
    for (int nt = 0; nt < NT; nt++){
        float v0 = acc[nt][0], v1 = acc[nt][1], v2 = acc[nt][2], v3 = acc[nt][3];
        if (ACT){ v0 = gelu_f(v0); v1 = gelu_f(v1); v2 = gelu_f(v2); v3 = gelu_f(v3); }
        unsigned u0 = pack_bf2(v0, v1), u1 = pack_bf2(v2, v3);
        asm volatile("st.shared.b32 [%0], %1;" :: "r"(oL0 + nt*16), "r"(u0));
        asm volatile("st.shared.b32 [%0], %1;" :: "r"(oL1 + nt*16), "r"(u1));
    }
}
template<int KS, int NT, bool ACT>
__device__ __forceinline__ void layer(uint32_t aLane, uint32_t wLane, int wStr,
                                      const float* bias, int t, uint32_t oL0, uint32_t oL1){
    float acc[NT][4];
    initacc<NT>(acc, bias, t);
    gemm<KS, NT>(acc, aLane, wLane, wStr);
    storeacc<NT, ACT>(acc, oL0, oL1);
}

/* ---------------------------------------------------------------------- */
__device__ void build_wt(__nv_bfloat16* dst, const float* __restrict__ W, int N, int K, int Kp,
                         int mode, int t, int stride){
    int total = N * K;
    for (int idx = t; idx < total; idx += stride){
        int n = idx / K, k = idx - n*K;
        int src = k;
        if (mode == 1) src = (k < 128) ? (64 + k) : ((k < 192) ? (k - 128) : k);
        dst[(size_t)n*Kp + k] = __float2bfloat16(W[(size_t)src*N + n]);
    }
}

__global__ void k_prep(const float* __restrict__ w1, const unsigned int* __restrict__ g32,
                       const float* __restrict__ enc_w2, const float* __restrict__ wy,
                       const float* __restrict__ wz,     const float* __restrict__ rz_w1,
                       const float* __restrict__ rz_w2,  const float* __restrict__ ry_w1,
                       const float* __restrict__ ry_w2,  const float* __restrict__ sel_w1,
                       const float* __restrict__ sel_w2){
    const int stride = gridDim.x * blockDim.x;
    const int t = blockIdx.x * blockDim.x + threadIdx.x;
    if (blockIdx.x == 0 && threadIdx.x < 32){
        unsigned v = 0;
        if (threadIdx.x < 16) v = g32[2*threadIdx.x + 1];
        unsigned any = __ballot_sync(0xffffffffu, v != 0u);
        if (threadIdx.x == 0) g_is64 = (any == 0u) ? 1 : 0;
    }
    {
        const float4* s = (const float4*)w1;
        unsigned* d = (unsigned*)g_w1e;
        for (int i = t; i < GG*NC*HID/4; i += stride){
            float4 v = s[i];
            unsigned short a, b;
            asm("cvt.rn.satfinite.e5m2x2.f32 %0, %1, %2;" : "=h"(a) : "f"(v.y), "f"(v.x));
            asm("cvt.rn.satfinite.e5m2x2.f32 %0, %1, %2;" : "=h"(b) : "f"(v.w), "f"(v.z));
            d[i] = (unsigned)a | ((unsigned)b << 16);
        }
    }
    build_wt(g_wt + WT_ENC2/2, enc_w2, 128, 128, 136, 0, t, stride);
    build_wt(g_wt + WT_WY/2,   wy,     128, 128, 136, 0, t, stride);
    build_wt(g_wt + WT_WZ/2,   wz,      64, 128, 136, 0, t, stride);
    build_wt(g_wt + WT_RZ1/2,  rz_w1,   64, 208, 216, 0, t, stride);
    build_wt(g_wt + WT_RZ2/2,  rz_w2,   64,  64,  72, 0, t, stride);
    build_wt(g_wt + WT_RY1/2,  ry_w1,   64, 208, 216, 1, t, stride);
    build_wt(g_wt + WT_RY2/2,  ry_w2,  128,  64,  72, 0, t, stride);
    build_wt(g_wt + WT_SEL1/2, sel_w1,  64, 128, 136, 0, t, stride);
    build_wt(g_wt + WT_SEL2/2, sel_w2,  64,  64,  72, 0, t, stride);
}

/* ---------------------------------------------------------------------- */
/* Fused kernel: phase A = enc1 with inline grid->colors conversion,      */
/* phase B = 13 mma layers, 16 warps (N-quarter split). Validated R15.    */
/* ---------------------------------------------------------------------- */
__global__ __launch_bounds__(512, 1) void k_main(
    const unsigned int* __restrict__ grid_raw,
    const float* __restrict__ b1,
    const float* __restrict__ gfeat, const float* __restrict__ gum,
    const float* __restrict__ enc_b2, const float* __restrict__ by,
    const float* __restrict__ bz,     const float* __restrict__ rz_b1,
    const float* __restrict__ rz_b2,  const float* __restrict__ ry_b1,
    const float* __restrict__ ry_b2,  const float* __restrict__ sel_b1,
    const float* __restrict__ sel_b2,
    float* __restrict__ out)
{
    extern __shared__ char smem[];
    const int tid = threadIdx.x;
    const int lane = tid & 31, wp = tid >> 5;      /* wp: 0..15 */
    const int b0 = blockIdx.x * 64;
    const uint32_t su = (uint32_t)__cvta_generic_to_shared(smem);

    /* ---- stage persistent refine weights ---- */
    cpa(su + RS_RZ1, (const char*)g_wt + WT_RZ1, 27648, tid, 512);
    cpa(su + RS_RZ2, (const char*)g_wt + WT_RZ2,  9216, tid, 512);
    cpa(su + RS_RY1, (const char*)g_wt + WT_RY1, 27648, tid, 512);
    cpa(su + RS_RY2, (const char*)g_wt + WT_RY2, 18432, tid, 512);
    CP_COMMIT();

    /* ================= phase A: enc1 gather ================= */
    {
        unsigned char* colors = (unsigned char*)(smem + E1_COLORS);
        const int q = lane & 7, bt = lane >> 3;
        const int r = wp*4 + bt;                   /* this thread's batch row */
        const unsigned ONESH = 0x3C003C00u;
        const int is64v = g_is64;

        /* convert 4 cells of own row for chunk window s */
        auto cvt_colors = [&](int s){
            int cell0 = s*E1_CHUNK + q*4;
            if (cell0 >= GG) return;
            unsigned char c4[4];
            if (is64v){
                const unsigned long long* gp =
                    (const unsigned long long*)grid_raw + (size_t)(b0 + r)*GG + cell0;
                #pragma unroll
                for (int j = 0; j < 4; j++)
                    c4[j] = (cell0 + j < GG) ? (unsigned char)gp[j] : 0;
            } else {
                const unsigned* gp = grid_raw + (size_t)(b0 + r)*GG + cell0;
                #pragma unroll
                for (int j = 0; j < 4; j++)
                    c4[j] = (cell0 + j < GG) ? (unsigned char)gp[j] : 0;
            }
            if (cell0 + 3 < GG){
                *(uchar4*)(colors + r*E1_CPAD + cell0) = make_uchar4(c4[0], c4[1], c4[2], c4[3]);
            } else {
                for (int j = 0; j < 4 && cell0 + j < GG; j++)
                    colors[r*E1_CPAD + cell0 + j] = c4[j];
            }
        };

        const char* wsrc = (const char*)g_w1e;
        auto issue = [&](int s){
            int base = s * E1_CHUNK;
            if (base < GG){
                int cells = min(E1_CHUNK, GG - base);
                int bytes = cells * E1_ROWB;
                unsigned dbase = su + (s & 1) * E1_STAGE;
                const char* sbase = wsrc + (size_t)base * E1_ROWB;
                for (int off = tid*16; off < bytes; off += 512*16) cp16(dbase + off, sbase + off);
            }
            CP_COMMIT();
        };

        unsigned acc[8];
        #pragma unroll
        for (int k = 0; k < 8; k++) acc[k] = 0u;

        cvt_colors(0); cvt_colors(1);
        issue(0); issue(1);
        const int NST = (GG + E1_CHUNK - 1) / E1_CHUNK;
        const unsigned char* crow = colors + r*E1_CPAD;

        auto sub16 = [&](const char* rbuf, int coff, int cellbase){
            uint4 cw = *(const uint4*)(crow + cellbase);
            unsigned cb[16];
            #pragma unroll
            for (int i = 0; i < 4; i++){
                cb[i]      = (cw.x >> (8*i)) & 0xFFu;
                cb[4 + i]  = (cw.y >> (8*i)) & 0xFFu;
                cb[8 + i]  = (cw.z >> (8*i)) & 0xFFu;
                cb[12 + i] = (cw.w >> (8*i)) & 0xFFu;
            }
            uint4 v[16];
            #pragma unroll
            for (int ci = 0; ci < 16; ci++)
                v[ci] = *(const uint4*)(rbuf + (coff + ci)*E1_ROWB + cb[ci]*HID + q*16);
            #pragma unroll
            for (int ci = 0; ci < 16; ci++){
                acc[0] = hfma2(prmt(v[ci].x, 0x1404u), ONESH, acc[0]);
                acc[1] = hfma2(prmt(v[ci].x, 0x3424u), ONESH, acc[1]);
                acc[2] = hfma2(prmt(v[ci].y, 0x1404u), ONESH, acc[2]);
                acc[3] = hfma2(prmt(v[ci].y, 0x3424u), ONESH, acc[3]);
                acc[4] = hfma2(prmt(v[ci].z, 0x1404u), ONESH, acc[4]);
                acc[5] = hfma2(prmt(v[ci].z, 0x3424u), ONESH, acc[5]);
                acc[6] = hfma2(prmt(v[ci].w, 0x1404u), ONESH, acc[6]);
                acc[7] = hfma2(prmt(v[ci].w, 0x3424u), ONESH, acc[7]);
            }
        };

        for (int s = 0; s < NST; s++){
            asm volatile("cp.async.wait_group 1;" ::: "memory");
            __syncthreads();
            const char* rbuf = smem + (s & 1) * E1_STAGE;
            const int cbase = s * E1_CHUNK;
            const int cells = min(E1_CHUNK, GG - cbase);
            if (cells == E1_CHUNK){
                sub16(rbuf, 0,  cbase);
                sub16(rbuf, 16, cbase + 16);
            } else {
                for (int ci = 0; ci < cells; ci++){
                    unsigned c = crow[cbase + ci];
                    uint4 vv = *(const uint4*)(rbuf + ci*E1_ROWB + c*HID + q*16);
                    acc[0] = hfma2(prmt(vv.x, 0x1404u), ONESH, acc[0]);
                    acc[1] = hfma2(prmt(vv.x, 0x3424u), ONESH, acc[1]);
                    acc[2] = hfma2(prmt(vv.y, 0x1404u), ONESH, acc[2]);
                    acc[3] = hfma2(prmt(vv.y, 0x3424u), ONESH, acc[3]);
                    acc[4] = hfma2(prmt(vv.z, 0x1404u), ONESH, acc[4]);
                    acc[5] = hfma2(prmt(vv.z, 0x3424u), ONESH, acc[5]);
                    acc[6] = hfma2(prmt(vv.w, 0x1404u), ONESH, acc[6]);
                    acc[7] = hfma2(prmt(vv.w, 0x3424u), ONESH, acc[7]);
                }
            }
            cvt_colors(s + 2);
            __syncthreads();
            issue(s + 2);
        }

        CP_WAIT(0);
        __syncthreads();

        /* h1 -> RS_H1 (bf16 rows, stride 272), +bias, gelu */
        {
            unsigned pk[8];
            #pragma unroll
            for (int k = 0; k < 8; k++){
                __half2 h = *(const __half2*)&acc[k];
                float f0 = __low2float(h)  + __ldg(b1 + q*16 + 2*k);
                float f1 = __high2float(h) + __ldg(b1 + q*16 + 2*k + 1);
                pk[k] = pack_bf2(gelu_f(f0), gelu_f(f1));
            }
            char* dst = smem + RS_H1 + r*272 + q*32;
            *(uint4*)(dst)      = make_uint4(pk[0], pk[1], pk[2], pk[3]);
            *(uint4*)(dst + 16) = make_uint4(pk[4], pk[5], pk[6], pk[7]);
        }
    }

    /* ================= phase B: 13 mma layers, 16 warps ================= */
    float* bs = (float*)smem;
    if (tid < 128){
        bs[BO_ENC2 + tid] = enc_b2[tid];
        bs[BO_Y + tid]    = by[tid];
        bs[BO_RY2 + tid]  = ry_b2[tid];
    }
    if (tid < 64){
        bs[BO_Z + tid]    = bz[tid];
        bs[BO_RZ1 + tid]  = rz_b1[tid];
        bs[BO_RZ2 + tid]  = rz_b2[tid];
        bs[BO_RY1 + tid]  = ry_b1[tid];
        bs[BO_SEL1 + tid] = sel_b1[tid];
        bs[BO_SEL2 + tid] = sel_b2[tid];
    }
    if (tid < 64){
        const float4* gp = (const float4*)(gfeat + (size_t)(b0 + tid)*16);
        float4 f0 = __ldg(gp), f1 = __ldg(gp+1), f2 = __ldg(gp+2), f3 = __ldg(gp+3);
        char* row = smem + RS_CAT + tid*432 + 384;
        *(uint4*)(row)      = make_uint4(pack_bf2(f0.x,f0.y), pack_bf2(f0.z,f0.w),
                                         pack_bf2(f1.x,f1.y), pack_bf2(f1.z,f1.w));
        *(uint4*)(row + 16) = make_uint4(pack_bf2(f2.x,f2.y), pack_bf2(f2.z,f2.w),
                                         pack_bf2(f3.x,f3.y), pack_bf2(f3.z,f3.w));
    }
    cpa(su + RS_WD0, (const char*)g_wt + WT_ENC2, 34816, tid, 512);
    CP_COMMIT();                                   /* A */
    cpa(su + RS_WD1, (const char*)g_wt + WT_WY, 34816, tid, 512);
    CP_COMMIT();                                   /* B */
    CP_WAIT(1);
    __syncthreads();

    const int quad = wp >> 2, h2 = wp & 3;
    const int t = lane & 3, g = lane >> 2;
    const uint32_t arow = (uint32_t)(lane & 15), ahalf = (uint32_t)((lane >> 4) * 16);
    const uint32_t brow = (uint32_t)(((lane >> 4) & 1)*8 + (lane & 7));
    const uint32_t bhalf = (uint32_t)(((lane >> 3) & 1) * 16);
    #define ALANE(base, str) ((base) + arow*(str) + ahalf)
    #define WLANE(base, str) ((base) + brow*(str) + bhalf)
    #define OLC(base, str, coff) ((base) + (uint32_t)g*(str) + (uint32_t)t*4 + (coff)), \
                                 ((base) + (uint32_t)(g+8)*(str) + (uint32_t)t*4 + (coff))

    const uint32_t H1q  = su + RS_H1  + quad*16*272;
    const uint32_t H2q  = su + RS_H2  + quad*16*272;
    const uint32_t CATq = su + RS_CAT + quad*16*432;
    const uint32_t Tq   = su + RS_T   + quad*16*144;

    layer<8,4,true>(ALANE(H1q,272), WLANE(su+RS_WD0 + h2*32*272, 272), 272,
                    bs+BO_ENC2 + h2*32, t, OLC(H2q,272,h2*64));
    __syncthreads();
    cpa(su + RS_H1,  (const char*)g_wt + WT_WZ,   17408, tid, 512); CP_COMMIT();  /* C */
    cpa(su + RS_WD0, (const char*)g_wt + WT_SEL1, 17408, tid, 512); CP_COMMIT();  /* D */
    CP_WAIT(2);
    __syncthreads();

    layer<8,4,false>(ALANE(H2q,272), WLANE(su+RS_WD1 + h2*32*272, 272), 272,
                     bs+BO_Y + h2*32, t, OLC(CATq,432,h2*64));
    CP_WAIT(1);
    __syncthreads();
    layer<8,2,false>(ALANE(H2q,272), WLANE(su+RS_H1 + h2*16*272, 272), 272,
                     bs+BO_Z + h2*16, t, OLC(CATq+256,432,h2*32));
    __syncthreads();
    cpa(su + RS_WD1, (const char*)g_wt + WT_SEL2, 9216, tid, 512); CP_COMMIT();   /* E */

    #pragma unroll 1
    for (int cyc = 0; cyc < 3; cyc++){
        layer<13,2,true >(ALANE(CATq,432), WLANE(su+RS_RZ1 + h2*16*432, 432), 432,
                          bs+BO_RZ1 + h2*16, t, OLC(Tq,144,h2*32));
        __syncthreads();
        layer<4, 2,false>(ALANE(Tq,144),   WLANE(su+RS_RZ2 + h2*16*144, 144), 144,
                          bs+BO_RZ2 + h2*16, t, OLC(CATq+256,432,h2*32));
        __syncthreads();
        layer<13,2,true >(ALANE(CATq,432), WLANE(su+RS_RY1 + h2*16*432, 432), 432,
                          bs+BO_RY1 + h2*16, t, OLC(Tq,144,h2*32));
        __syncthreads();
        layer<4, 4,false>(ALANE(Tq,144),   WLANE(su+RS_RY2 + h2*32*144, 144), 144,
                          bs+BO_RY2 + h2*32, t, OLC(CATq,432,h2*64));
        __syncthreads();
    }

    CP_WAIT(1);
    layer<8,2,true>(ALANE(CATq,432), WLANE(su+RS_WD0 + h2*16*272, 272), 272,
                    bs+BO_SEL1 + h2*16, t, OLC(Tq,144,h2*32));
    CP_WAIT(0);
    __syncthreads();

    {
        float acc[2][4];
        initacc<2>(acc, bs + BO_SEL2 + h2*16, t);
        gemm<4,2>(acc, ALANE(Tq,144), WLANE(su+RS_WD1 + h2*16*144, 144), 144);
        float* LG = (float*)(smem + RS_CAT);
        int r0l = quad*16 + g;
        #pragma unroll
        for (int nt = 0; nt < 2; nt++){
            int c = h2*16 + nt*8 + 2*t;
            LG[r0l*64 + c]       = acc[nt][0];
            LG[r0l*64 + c + 1]   = acc[nt][1];
            LG[(r0l+8)*64 + c]   = acc[nt][2];
            LG[(r0l+8)*64 + c+1] = acc[nt][3];
        }
    }
    __syncthreads();
    {
        const float* LG = (const float*)(smem + RS_CAT);
        int r = wp*4 + (lane >> 3);
        int c0 = (lane & 7) * 8;
        int bg = b0 + r;
        float v[8];
        #pragma unroll
        for (int j = 0; j < 8; j += 4){
            float4 gv = *(const float4*)(gum + (size_t)bg*64 + c0 + j);
            v[j]   = LG[r*64 + c0 + j]     + gv.x;
            v[j+1] = LG[r*64 + c0 + j + 1] + gv.y;
            v[j+2] = LG[r*64 + c0 + j + 2] + gv.z;
            v[j+3] = LG[r*64 + c0 + j + 3] + gv.w;
        }
        float m = v[0];
        #pragma unroll
        for (int j = 1; j < 8; j++) m = fmaxf(m, v[j]);
        m = fmaxf(m, __shfl_xor_sync(0xffffffffu, m, 1));
        m = fmaxf(m, __shfl_xor_sync(0xffffffffu, m, 2));
        m = fmaxf(m, __shfl_xor_sync(0xffffffffu, m, 4));
        float s = 0.0f;
        #pragma unroll
        for (int j = 0; j < 8; j++){ v[j] = expf(v[j] - m); s += v[j]; }
        s += __shfl_xor_sync(0xffffffffu, s, 1);
        s += __shfl_xor_sync(0xffffffffu, s, 2);
        s += __shfl_xor_sync(0xffffffffu, s, 4);
        float inv = 1.0f / s;
        *(float4*)(out + (size_t)bg*64 + c0)     = make_float4(v[0]*inv, v[1]*inv, v[2]*inv, v[3]*inv);
        *(float4*)(out + (size_t)bg*64 + c0 + 4) = make_float4(v[4]*inv, v[5]*inv, v[6]*inv, v[7]*inv);
    }
    #undef ALANE
    #undef WLANE
    #undef OLC
}

/* ---------------------------------------------------------------------- */
extern "C" void kernel_launch(void* const* d_in, const int* in_sizes, int n_in,
                              void* d_out, int out_size){
    const unsigned int* grid32 = (const unsigned int*)d_in[0];
    const float* gfeat  = (const float*)d_in[1];
    const float* gum    = (const float*)d_in[2];
    const float* enc_w1 = (const float*)d_in[3];
    const float* enc_b1 = (const float*)d_in[4];
    const float* enc_w2 = (const float*)d_in[5];
    const float* enc_b2 = (const float*)d_in[6];
    const float* wy     = (const float*)d_in[7];
    const float* by     = (const float*)d_in[8];
    const float* wz     = (const float*)d_in[9];
    const float* bz     = (const float*)d_in[10];
    const float* rz_w1  = (const float*)d_in[11];
    const float* rz_b1  = (const float*)d_in[12];
    const float* rz_w2  = (const float*)d_in[13];
    const float* rz_b2  = (const float*)d_in[14];
    const float* ry_w1  = (const float*)d_in[15];
    const float* ry_b1  = (const float*)d_in[16];
    const float* ry_w2  = (const float*)d_in[17];
    const float* ry_b2  = (const float*)d_in[18];
    const float* sel_w1 = (const float*)d_in[19];
    const float* sel_b1 = (const float*)d_in[20];
    const float* sel_w2 = (const float*)d_in[21];
    const float* sel_b2 = (const float*)d_in[22];
    float* out = (float*)d_out;

    cudaFuncSetAttribute(k_main, cudaFuncAttributeMaxDynamicSharedMemorySize, RS_TOTAL);

    k_prep<<<2048, 256>>>(enc_w1, grid32, enc_w2, wy, wz, rz_w1, rz_w2, ry_w1, ry_w2, sel_w1, sel_w2);
    k_main<<<BB/64, 512, RS_TOTAL>>>(grid32, enc_b1, gfeat, gum,
        enc_b2, by, bz, rz_b1, rz_b2, ry_b1, ry_b2, sel_b1, sel_b2, out);
    (void)in_sizes; (void)n_in; (void)out_size;
}

// round 17
// speedup vs baseline: 1.0137x; 1.0137x over previous
#include <cuda_runtime.h>
#include <cuda_bf16.h>
#include <cuda_fp16.h>
#include <stdint.h>

#define BB   8192
#define GG   900
#define NC   10
#define HID  128

/* ---- enc1 phase: e5m2 weights, 32-cell chunks ---- */
#define E1_CHUNK 32
#define E1_ROWB  (NC*HID)             /* 1280 */
#define E1_STAGE (E1_CHUNK*E1_ROWB)   /* 40960; buf0 @0, buf1 @40960 */
#define E1_COLORS (2*E1_STAGE)        /* colors @81920, 64*912 bytes */
#define E1_CPAD  912

/* ---- transposed padded weight blob W^T[N][K+8] bf16 (byte offsets) ---- */
#define WT_ENC2 0
#define WT_WY   34816
#define WT_WZ   69632
#define WT_RZ1  87040
#define WT_RZ2  114688
#define WT_RY1  123904
#define WT_RY2  151552
#define WT_SEL1 169984
#define WT_SEL2 187392
#define WT_TOTAL 196608

/* ---- fused SMEM (bytes) ---- */
#define RS_BIAS 0
#define RS_H1   3072
#define RS_H2   20480
#define RS_CAT  37888
#define RS_T    65536
#define RS_WD0  74752
#define RS_WD1  109568
#define RS_RZ1  144384
#define RS_RZ2  172032
#define RS_RY1  181248
#define RS_RY2  208896
#define RS_TOTAL 227328

#define BO_ENC2 0
#define BO_Y    128
#define BO_Z    256
#define BO_RZ1  320
#define BO_RZ2  384
#define BO_RY1  448
#define BO_RY2  512
#define BO_SEL1 640
#define BO_SEL2 704

static __device__ __align__(16) unsigned char g_w1e[GG*NC*HID];
static __device__ __align__(16) __nv_bfloat16 g_wt[WT_TOTAL/2];
static __device__ int g_is64;

__device__ __forceinline__ float gelu_f(float x){
    return 0.5f * x * (1.0f + erff(x * 0.7071067811865476f));
}
__device__ __forceinline__ unsigned pack_bf2(float lo, float hi){
    unsigned d; asm("cvt.rn.bf16x2.f32 %0, %1, %2;" : "=r"(d) : "f"(hi), "f"(lo)); return d;
}
__device__ __forceinline__ unsigned hfma2(unsigned a, unsigned b, unsigned c){
    unsigned d; asm("fma.rn.f16x2 %0, %1, %2, %3;" : "=r"(d) : "r"(a), "r"(b), "r"(c)); return d;
}
__device__ __forceinline__ unsigned prmt(unsigned v, unsigned sel){
    unsigned d; asm("prmt.b32 %0, %1, 0, %2;" : "=r"(d) : "r"(v), "r"(sel)); return d;
}

#define CP_COMMIT() asm volatile("cp.async.commit_group;" ::: "memory")
#define CP_WAIT(N)  asm volatile("cp.async.wait_group %0;" :: "n"(N) : "memory")

__device__ __forceinline__ void cp16(uint32_t d, const void* s){
    asm volatile("cp.async.ca.shared.global [%0], [%1], 16;" :: "r"(d), "l"(s));
}
__device__ __forceinline__ void cpa(uint32_t dst, const void* src, int bytes, int tid, int nthr){
    const char* s = (const char*)src;
    for (int off = tid*16; off < bytes; off += nthr*16) cp16(dst + off, s + off);
}

/* ---- mma.sync / ldmatrix ---- */
__device__ __forceinline__ uint4 ldm4(uint32_t a){
    uint4 r;
    asm volatile("ldmatrix.sync.aligned.m8n8.x4.shared.b16 {%0,%1,%2,%3}, [%4];"
        : "=r"(r.x), "=r"(r.y), "=r"(r.z), "=r"(r.w) : "r"(a));
    return r;
}
__device__ __forceinline__ void mma16816(float (&c)[4], const uint4& a, uint32_t b0, uint32_t b1){
    asm volatile("mma.sync.aligned.m16n8k16.row.col.f32.bf16.bf16.f32 "
        "{%0,%1,%2,%3},{%4,%5,%6,%7},{%8,%9},{%0,%1,%2,%3};"
        : "+f"(c[0]), "+f"(c[1]), "+f"(c[2]), "+f"(c[3])
        : "r"(a.x), "r"(a.y), "r"(a.z), "r"(a.w), "r"(b0), "r"(b1));
}

template<int KS, int NT>
__device__ __forceinline__ void gemm(float (&acc)[NT][4], uint32_t aLane, uint32_t wLane, int wStr){
    #pragma unroll
    for (int ks = 0; ks < KS; ks++){
        uint4 A = ldm4(aLane + ks*32);
        #pragma unroll
        for (int p = 0; p < NT/2; p++){
            uint4 B = ldm4(wLane + p*16*wStr + ks*32);
            mma16816(acc[2*p],   A, B.x, B.y);
            mma16816(acc[2*p+1], A, B.z, B.w);
        }
    }
}
template<int NT>
__device__ __forceinline__ void initacc(float (&acc)[NT][4], const float* bias, int t){
    #pragma unroll
    for (int nt = 0; nt < NT; nt++){
        float b0 = bias[nt*8 + 2*t], b1 = bias[nt*8 + 2*t + 1];
        acc[nt][0] = b0; acc[nt][1] = b1; acc[nt][2] = b0; acc[nt][3] = b1;
    }
}
template<int NT, bool ACT>
__device__ __forceinline__ void storeacc(float (&acc)[NT][4], uint32_t oL0, uint32_t oL1){
    #pragma unroll
    for (int nt = 0; nt < NT; nt++){
        float v0 = acc[nt][0], v1 = acc[nt][1], v2 = acc[nt][2], v3 = acc[nt][3];
        if (ACT){ v0 = gelu_f(v0); v1 = gelu_f(v1); v2 = gelu_f(v2); v3 = gelu_f(v3); }
        unsigned u0 = pack_bf2(v0, v1), u1 = pack_bf2(v2, v3);
        asm volatile("st.shared.b32 [%0], %1;" :: "r"(oL0 + nt*16), "r"(u0));
        asm volatile("st.shared.b32 [%0], %1;" :: "r"(oL1 + nt*16), "r"(u1));
    }
}
template<int KS, int NT, bool ACT>
__device__ __forceinline__ void layer(uint32_t aLane, uint32_t wLane, int wStr,
                                      const float* bias, int t, uint32_t oL0, uint32_t oL1){
    float acc[NT][4];
    initacc<NT>(acc, bias, t);
    gemm<KS, NT>(acc, aLane, wLane, wStr);
    storeacc<NT, ACT>(acc, oL0, oL1);
}

/* ---------------------------------------------------------------------- */
__device__ void build_wt(__nv_bfloat16* dst, const float* __restrict__ W, int N, int K, int Kp,
                         int mode, int t, int stride){
    int total = N * K;
    for (int idx = t; idx < total; idx += stride){
        int n = idx / K, k = idx - n*K;
        int src = k;
        if (mode == 1) src = (k < 128) ? (64 + k) : ((k < 192) ? (k - 128) : k);
        dst[(size_t)n*Kp + k] = __float2bfloat16(W[(size_t)src*N + n]);
    }
}

__global__ void k_prep(const float* __restrict__ w1, const unsigned int* __restrict__ g32,
                       const float* __restrict__ enc_w2, const float* __restrict__ wy,
                       const float* __restrict__ wz,     const float* __restrict__ rz_w1,
                       const float* __restrict__ rz_w2,  const float* __restrict__ ry_w1,
                       const float* __restrict__ ry_w2,  const float* __restrict__ sel_w1,
                       const float* __restrict__ sel_w2){
    const int stride = gridDim.x * blockDim.x;
    const int t = blockIdx.x * blockDim.x + threadIdx.x;
    if (blockIdx.x == 0 && threadIdx.x < 32){
        unsigned v = 0;
        if (threadIdx.x < 16) v = g32[2*threadIdx.x + 1];
        unsigned any = __ballot_sync(0xffffffffu, v != 0u);
        if (threadIdx.x == 0) g_is64 = (any == 0u) ? 1 : 0;
    }
    {
        const float4* s = (const float4*)w1;
        unsigned* d = (unsigned*)g_w1e;
        for (int i = t; i < GG*NC*HID/4; i += stride){
            float4 v = s[i];
            unsigned short a, b;
            asm("cvt.rn.satfinite.e5m2x2.f32 %0, %1, %2;" : "=h"(a) : "f"(v.y), "f"(v.x));
            asm("cvt.rn.satfinite.e5m2x2.f32 %0, %1, %2;" : "=h"(b) : "f"(v.w), "f"(v.z));
            d[i] = (unsigned)a | ((unsigned)b << 16);
        }
    }
    build_wt(g_wt + WT_ENC2/2, enc_w2, 128, 128, 136, 0, t, stride);
    build_wt(g_wt + WT_WY/2,   wy,     128, 128, 136, 0, t, stride);
    build_wt(g_wt + WT_WZ/2,   wz,      64, 128, 136, 0, t, stride);
    build_wt(g_wt + WT_RZ1/2,  rz_w1,   64, 208, 216, 0, t, stride);
    build_wt(g_wt + WT_RZ2/2,  rz_w2,   64,  64,  72, 0, t, stride);
    build_wt(g_wt + WT_RY1/2,  ry_w1,   64, 208, 216, 1, t, stride);
    build_wt(g_wt + WT_RY2/2,  ry_w2,  128,  64,  72, 0, t, stride);
    build_wt(g_wt + WT_SEL1/2, sel_w1,  64, 128, 136, 0, t, stride);
    build_wt(g_wt + WT_SEL2/2, sel_w2,  64,  64,  72, 0, t, stride);
}

/* ---------------------------------------------------------------------- */
/* Fused kernel: phase A = enc1 with inline grid->colors conversion       */
/* (loads hoisted ABOVE compute, stores after), phase B = 13 mma layers.  */
/* ---------------------------------------------------------------------- */
__global__ __launch_bounds__(512, 1) void k_main(
    const unsigned int* __restrict__ grid_raw,
    const float* __restrict__ b1,
    const float* __restrict__ gfeat, const float* __restrict__ gum,
    const float* __restrict__ enc_b2, const float* __restrict__ by,
    const float* __restrict__ bz,     const float* __restrict__ rz_b1,
    const float* __restrict__ rz_b2,  const float* __restrict__ ry_b1,
    const float* __restrict__ ry_b2,  const float* __restrict__ sel_b1,
    const float* __restrict__ sel_b2,
    float* __restrict__ out)
{
    extern __shared__ char smem[];
    const int tid = threadIdx.x;
    const int lane = tid & 31, wp = tid >> 5;      /* wp: 0..15 */
    const int b0 = blockIdx.x * 64;
    const uint32_t su = (uint32_t)__cvta_generic_to_shared(smem);

    /* ---- stage persistent refine weights ---- */
    cpa(su + RS_RZ1, (const char*)g_wt + WT_RZ1, 27648, tid, 512);
    cpa(su + RS_RZ2, (const char*)g_wt + WT_RZ2,  9216, tid, 512);
    cpa(su + RS_RY1, (const char*)g_wt + WT_RY1, 27648, tid, 512);
    cpa(su + RS_RY2, (const char*)g_wt + WT_RY2, 18432, tid, 512);
    CP_COMMIT();

    /* ================= phase A: enc1 gather ================= */
    {
        unsigned char* colors = (unsigned char*)(smem + E1_COLORS);
        const int q = lane & 7, bt = lane >> 3;
        const int r = wp*4 + bt;                   /* this thread's batch row */
        const unsigned ONESH = 0x3C003C00u;
        const int is64v = g_is64;

        /* load 4 cells of own row for chunk window s into regs */
        auto cvt_load = [&](int s, unsigned char (&c4)[4]){
            int cell0 = s*E1_CHUNK + q*4;
            if (cell0 >= GG) return false;
            if (is64v){
                const unsigned long long* gp =
                    (const unsigned long long*)grid_raw + (size_t)(b0 + r)*GG + cell0;
                #pragma unroll
                for (int j = 0; j < 4; j++)
                    c4[j] = (cell0 + j < GG) ? (unsigned char)__ldg(gp + j) : 0;
            } else {
                const unsigned* gp = grid_raw + (size_t)(b0 + r)*GG + cell0;
                #pragma unroll
                for (int j = 0; j < 4; j++)
                    c4[j] = (cell0 + j < GG) ? (unsigned char)__ldg(gp + j) : 0;
            }
            return true;
        };
        auto cvt_store = [&](int s, const unsigned char (&c4)[4]){
            int cell0 = s*E1_CHUNK + q*4;
            if (cell0 + 3 < GG){
                *(uchar4*)(colors + r*E1_CPAD + cell0) = make_uchar4(c4[0], c4[1], c4[2], c4[3]);
            } else {
                for (int j = 0; j < 4 && cell0 + j < GG; j++)
                    colors[r*E1_CPAD + cell0 + j] = c4[j];
            }
        };

        const char* wsrc = (const char*)g_w1e;
        auto issue = [&](int s){
            int base = s * E1_CHUNK;
            if (base < GG){
                int cells = min(E1_CHUNK, GG - base);
                int bytes = cells * E1_ROWB;
                unsigned dbase = su + (s & 1) * E1_STAGE;
                const char* sbase = wsrc + (size_t)base * E1_ROWB;
                for (int off = tid*16; off < bytes; off += 512*16) cp16(dbase + off, sbase + off);
            }
            CP_COMMIT();
        };

        unsigned acc[8];
        #pragma unroll
        for (int k = 0; k < 8; k++) acc[k] = 0u;

        /* prologue: convert windows 0,1 fully */
        {
            unsigned char c4[4];
            if (cvt_load(0, c4)) cvt_store(0, c4);
            if (cvt_load(1, c4)) cvt_store(1, c4);
        }
        issue(0); issue(1);
        const int NST = (GG + E1_CHUNK - 1) / E1_CHUNK;
        const unsigned char* crow = colors + r*E1_CPAD;

        auto sub16 = [&](const char* rbuf, int coff, int cellbase){
            uint4 cw = *(const uint4*)(crow + cellbase);
            unsigned cb[16];
            #pragma unroll
            for (int i = 0; i < 4; i++){
                cb[i]      = (cw.x >> (8*i)) & 0xFFu;
                cb[4 + i]  = (cw.y >> (8*i)) & 0xFFu;
                cb[8 + i]  = (cw.z >> (8*i)) & 0xFFu;
                cb[12 + i] = (cw.w >> (8*i)) & 0xFFu;
            }
            uint4 v[16];
            #pragma unroll
            for (int ci = 0; ci < 16; ci++)
                v[ci] = *(const uint4*)(rbuf + (coff + ci)*E1_ROWB + cb[ci]*HID + q*16);
            #pragma unroll
            for (int ci = 0; ci < 16; ci++){
                acc[0] = hfma2(prmt(v[ci].x, 0x1404u), ONESH, acc[0]);
                acc[1] = hfma2(prmt(v[ci].x, 0x3424u), ONESH, acc[1]);
                acc[2] = hfma2(prmt(v[ci].y, 0x1404u), ONESH, acc[2]);
                acc[3] = hfma2(prmt(v[ci].y, 0x3424u), ONESH, acc[3]);
                acc[4] = hfma2(prmt(v[ci].z, 0x1404u), ONESH, acc[4]);
                acc[5] = hfma2(prmt(v[ci].z, 0x3424u), ONESH, acc[5]);
                acc[6] = hfma2(prmt(v[ci].w, 0x1404u), ONESH, acc[6]);
                acc[7] = hfma2(prmt(v[ci].w, 0x3424u), ONESH, acc[7]);
            }
        };

        for (int s = 0; s < NST; s++){
            asm volatile("cp.async.wait_group 1;" ::: "memory");
            __syncthreads();
            /* hoist next-window grid loads ABOVE the compute (DRAM hidden) */
            unsigned char nc4[4];
            bool have = cvt_load(s + 2, nc4);

            const char* rbuf = smem + (s & 1) * E1_STAGE;
            const int cbase = s * E1_CHUNK;
            const int cells = min(E1_CHUNK, GG - cbase);
            if (cells == E1_CHUNK){
                sub16(rbuf, 0,  cbase);
                sub16(rbuf, 16, cbase + 16);
            } else {
                for (int ci = 0; ci < cells; ci++){
                    unsigned c = crow[cbase + ci];
                    uint4 vv = *(const uint4*)(rbuf + ci*E1_ROWB + c*HID + q*16);
                    acc[0] = hfma2(prmt(vv.x, 0x1404u), ONESH, acc[0]);
                    acc[1] = hfma2(prmt(vv.x, 0x3424u), ONESH, acc[1]);
                    acc[2] = hfma2(prmt(vv.y, 0x1404u), ONESH, acc[2]);
                    acc[3] = hfma2(prmt(vv.y, 0x3424u), ONESH, acc[3]);
                    acc[4] = hfma2(prmt(vv.z, 0x1404u), ONESH, acc[4]);
                    acc[5] = hfma2(prmt(vv.z, 0x3424u), ONESH, acc[5]);
                    acc[6] = hfma2(prmt(vv.w, 0x1404u), ONESH, acc[6]);
                    acc[7] = hfma2(prmt(vv.w, 0x3424u), ONESH, acc[7]);
                }
            }
            if (have) cvt_store(s + 2, nc4);
            __syncthreads();
            issue(s + 2);
        }

        CP_WAIT(0);
        __syncthreads();

        /* h1 -> RS_H1 (bf16 rows, stride 272), +bias, gelu */
        {
            unsigned pk[8];
            #pragma unroll
            for (int k = 0; k < 8; k++){
                __half2 h = *(const __half2*)&acc[k];
                float f0 = __low2float(h)  + __ldg(b1 + q*16 + 2*k);
                float f1 = __high2float(h) + __ldg(b1 + q*16 + 2*k + 1);
                pk[k] = pack_bf2(gelu_f(f0), gelu_f(f1));
            }
            char* dst = smem + RS_H1 + r*272 + q*32;
            *(uint4*)(dst)      = make_uint4(pk[0], pk[1], pk[2], pk[3]);
            *(uint4*)(dst + 16) = make_uint4(pk[4], pk[5], pk[6], pk[7]);
        }
    }

    /* ================= phase B: 13 mma layers, 16 warps ================= */
    float* bs = (float*)smem;
    if (tid < 128){
        bs[BO_ENC2 + tid] = enc_b2[tid];
        bs[BO_Y + tid]    = by[tid];
        bs[BO_RY2 + tid]  = ry_b2[tid];
    }
    if (tid < 64){
        bs[BO_Z + tid]    = bz[tid];
        bs[BO_RZ1 + tid]  = rz_b1[tid];
        bs[BO_RZ2 + tid]  = rz_b2[tid];
        bs[BO_RY1 + tid]  = ry_b1[tid];
        bs[BO_SEL1 + tid] = sel_b1[tid];
        bs[BO_SEL2 + tid] = sel_b2[tid];
    }
    if (tid < 64){
        const float4* gp = (const float4*)(gfeat + (size_t)(b0 + tid)*16);
        float4 f0 = __ldg(gp), f1 = __ldg(gp+1), f2 = __ldg(gp+2), f3 = __ldg(gp+3);
        char* row = smem + RS_CAT + tid*432 + 384;
        *(uint4*)(row)      = make_uint4(pack_bf2(f0.x,f0.y), pack_bf2(f0.z,f0.w),
                                         pack_bf2(f1.x,f1.y), pack_bf2(f1.z,f1.w));
        *(uint4*)(row + 16) = make_uint4(pack_bf2(f2.x,f2.y), pack_bf2(f2.z,f2.w),
                                         pack_bf2(f3.x,f3.y), pack_bf2(f3.z,f3.w));
    }
    cpa(su + RS_WD0, (const char*)g_wt + WT_ENC2, 34816, tid, 512);
    CP_COMMIT();                                   /* A */
    cpa(su + RS_WD1, (const char*)g_wt + WT_WY, 34816, tid, 512);
    CP_COMMIT();                                   /* B */
    CP_WAIT(1);
    __syncthreads();

    const int quad = wp >> 2, h2 = wp & 3;
    const int t = lane & 3, g = lane >> 2;
    const uint32_t arow = (uint32_t)(lane & 15), ahalf = (uint32_t)((lane >> 4) * 16);
    const uint32_t brow = (uint32_t)(((lane >> 4) & 1)*8 + (lane & 7));
    const uint32_t bhalf = (uint32_t)(((lane >> 3) & 1) * 16);
    #define ALANE(base, str) ((base) + arow*(str) + ahalf)
    #define WLANE(base, str) ((base) + brow*(str) + bhalf)
    #define OLC(base, str, coff) ((base) + (uint32_t)g*(str) + (uint32_t)t*4 + (coff)), \
                                 ((base) + (uint32_t)(g+8)*(str) + (uint32_t)t*4 + (coff))

    const uint32_t H1q  = su + RS_H1  + quad*16*272;
    const uint32_t H2q  = su + RS_H2  + quad*16*272;
    const uint32_t CATq = su + RS_CAT + quad*16*432;
    const uint32_t Tq   = su + RS_T   + quad*16*144;

    layer<8,4,true>(ALANE(H1q,272), WLANE(su+RS_WD0 + h2*32*272, 272), 272,
                    bs+BO_ENC2 + h2*32, t, OLC(H2q,272,h2*64));
    __syncthreads();
    cpa(su + RS_H1,  (const char*)g_wt + WT_WZ,   17408, tid, 512); CP_COMMIT();  /* C */
    cpa(su + RS_WD0, (const char*)g_wt + WT_SEL1, 17408, tid, 512); CP_COMMIT();  /* D */
    CP_WAIT(2);
    __syncthreads();

    layer<8,4,false>(ALANE(H2q,272), WLANE(su+RS_WD1 + h2*32*272, 272), 272,
                     bs+BO_Y + h2*32, t, OLC(CATq,432,h2*64));
    CP_WAIT(1);
    __syncthreads();
    layer<8,2,false>(ALANE(H2q,272), WLANE(su+RS_H1 + h2*16*272, 272), 272,
                     bs+BO_Z + h2*16, t, OLC(CATq+256,432,h2*32));
    __syncthreads();
    cpa(su + RS_WD1, (const char*)g_wt + WT_SEL2, 9216, tid, 512); CP_COMMIT();   /* E */

    #pragma unroll 1
    for (int cyc = 0; cyc < 3; cyc++){
        layer<13,2,true >(ALANE(CATq,432), WLANE(su+RS_RZ1 + h2*16*432, 432), 432,
                          bs+BO_RZ1 + h2*16, t, OLC(Tq,144,h2*32));
        __syncthreads();
        layer<4, 2,false>(ALANE(Tq,144),   WLANE(su+RS_RZ2 + h2*16*144, 144), 144,
                          bs+BO_RZ2 + h2*16, t, OLC(CATq+256,432,h2*32));
        __syncthreads();
        layer<13,2,true >(ALANE(CATq,432), WLANE(su+RS_RY1 + h2*16*432, 432), 432,
                          bs+BO_RY1 + h2*16, t, OLC(Tq,144,h2*32));
        __syncthreads();
        layer<4, 4,false>(ALANE(Tq,144),   WLANE(su+RS_RY2 + h2*32*144, 144), 144,
                          bs+BO_RY2 + h2*32, t, OLC(CATq,432,h2*64));
        __syncthreads();
    }

    CP_WAIT(1);
    layer<8,2,true>(ALANE(CATq,432), WLANE(su+RS_WD0 + h2*16*272, 272), 272,
                    bs+BO_SEL1 + h2*16, t, OLC(Tq,144,h2*32));
    CP_WAIT(0);
    __syncthreads();

    {
        float acc[2][4];
        initacc<2>(acc, bs + BO_SEL2 + h2*16, t);
        gemm<4,2>(acc, ALANE(Tq,144), WLANE(su+RS_WD1 + h2*16*144, 144), 144);
        float* LG = (float*)(smem + RS_CAT);
        int r0l = quad*16 + g;
        #pragma unroll
        for (int nt = 0; nt < 2; nt++){
            int c = h2*16 + nt*8 + 2*t;
            LG[r0l*64 + c]       = acc[nt][0];
            LG[r0l*64 + c + 1]   = acc[nt][1];
            LG[(r0l+8)*64 + c]   = acc[nt][2];
            LG[(r0l+8)*64 + c+1] = acc[nt][3];
        }
    }
    __syncthreads();
    {
        const float* LG = (const float*)(smem + RS_CAT);
        int r = wp*4 + (lane >> 3);
        int c0 = (lane & 7) * 8;
        int bg = b0 + r;
        float v[8];
        #pragma unroll
        for (int j = 0; j < 8; j += 4){
            float4 gv = *(const float4*)(gum + (size_t)bg*64 + c0 + j);
            v[j]   = LG[r*64 + c0 + j]     + gv.x;
            v[j+1] = LG[r*64 + c0 + j + 1] + gv.y;
            v[j+2] = LG[r*64 + c0 + j + 2] + gv.z;
            v[j+3] = LG[r*64 + c0 + j + 3] + gv.w;
        }
        float m = v[0];
        #pragma unroll
        for (int j = 1; j < 8; j++) m = fmaxf(m, v[j]);
        m = fmaxf(m, __shfl_xor_sync(0xffffffffu, m, 1));
        m = fmaxf(m, __shfl_xor_sync(0xffffffffu, m, 2));
        m = fmaxf(m, __shfl_xor_sync(0xffffffffu, m, 4));
        float s = 0.0f;
        #pragma unroll
        for (int j = 0; j < 8; j++){ v[j] = expf(v[j] - m); s += v[j]; }
        s += __shfl_xor_sync(0xffffffffu, s, 1);
        s += __shfl_xor_sync(0xffffffffu, s, 2);
        s += __shfl_xor_sync(0xffffffffu, s, 4);
        float inv = 1.0f / s;
        *(float4*)(out + (size_t)bg*64 + c0)     = make_float4(v[0]*inv, v[1]*inv, v[2]*inv, v[3]*inv);
        *(float4*)(out + (size_t)bg*64 + c0 + 4) = make_float4(v[4]*inv, v[5]*inv, v[6]*inv, v[7]*inv);
    }
    #undef ALANE
    #undef WLANE
    #undef OLC
}

/* ---------------------------------------------------------------------- */
extern "C" void kernel_launch(void* const* d_in, const int* in_sizes, int n_in,
                              void* d_out, int out_size){
    const unsigned int* grid32 = (const unsigned int*)d_in[0];
    const float* gfeat  = (const float*)d_in[1];
    const float* gum    = (const float*)d_in[2];
    const float* enc_w1 = (const float*)d_in[3];
    const float* enc_b1 = (const float*)d_in[4];
    const float* enc_w2 = (const float*)d_in[5];
    const float* enc_b2 = (const float*)d_in[6];
    const float* wy     = (const float*)d_in[7];
    const float* by     = (const float*)d_in[8];
    const float* wz     = (const float*)d_in[9];
    const float* bz     = (const float*)d_in[10];
    const float* rz_w1  = (const float*)d_in[11];
    const float* rz_b1  = (const float*)d_in[12];
    const float* rz_w2  = (const float*)d_in[13];
    const float* rz_b2  = (const float*)d_in[14];
    const float* ry_w1  = (const float*)d_in[15];
    const float* ry_b1  = (const float*)d_in[16];
    const float* ry_w2  = (const float*)d_in[17];
    const float* ry_b2  = (const float*)d_in[18];
    const float* sel_w1 = (const float*)d_in[19];
    const float* sel_b1 = (const float*)d_in[20];
    const float* sel_w2 = (const float*)d_in[21];
    const float* sel_b2 = (const float*)d_in[22];
    float* out = (float*)d_out;

    cudaFuncSetAttribute(k_main, cudaFuncAttributeMaxDynamicSharedMemorySize, RS_TOTAL);

    k_prep<<<2048, 256>>>(enc_w1, grid32, enc_w2, wy, wz, rz_w1, rz_w2, ry_w1, ry_w2, sel_w1, sel_w2);
    k_main<<<BB/64, 512, RS_TOTAL>>>(grid32, enc_b1, gfeat, gum,
        enc_b2, by, bz, rz_b1, rz_b2, ry_b1, ry_b2, sel_b1, sel_b2, out);
    (void)in_sizes; (void)n_in; (void)out_size;
}